// round 3
// baseline (speedup 1.0000x reference)
#include <cuda_runtime.h>
#include <math_constants.h>
#include <math.h>

#define Bsz   4
#define SEQ   2048
#define Dm    512
#define NH    8
#define Dh    64
#define TOPK  10
#define BH    (Bsz*NH)                 // 32
#define CTX_ELEMS ((size_t)Bsz*SEQ*Dm) // 4,194,304

// Scratch for projected Q/K/V in head-major layout [B*H][S][64]
__device__ float g_Q[BH*SEQ*Dh];
__device__ float g_K[BH*SEQ*Dh];
__device__ float g_V[BH*SEQ*Dh];

// ---------------------------------------------------------------------------
// QKV projection: out[b,h,s,dd] = sum_k x[b,s,k] * W[h*64+dd, k] + bias
// CRITICAL: accumulation is a single in-order FMA chain over k=0..511
// (canonical GEMM rounding -> bit-match reference microkernels).
// ---------------------------------------------------------------------------
__global__ __launch_bounds__(256) void qkv_gemm(
    const float* __restrict__ x,
    const float* __restrict__ Wq, const float* __restrict__ bq,
    const float* __restrict__ Wk, const float* __restrict__ bk,
    const float* __restrict__ Wv, const float* __restrict__ bv)
{
    const float* W; const float* bias; float* out;
    if (blockIdx.z == 0)      { W = Wq; bias = bq; out = g_Q; }
    else if (blockIdx.z == 1) { W = Wk; bias = bk; out = g_K; }
    else                      { W = Wv; bias = bv; out = g_V; }

    __shared__ float xs[32*132];  // xs[kc][row], row<128, pad 132
    __shared__ float ws[32*68];   // ws[kc][col], col<64,  pad 68

    int tid = threadIdx.x;
    int tx = tid & 15, ty = tid >> 4;
    int m0 = blockIdx.y * 128;
    int n0 = blockIdx.x * 64;
    int head = blockIdx.x;

    float acc[8][4];
    #pragma unroll
    for (int i = 0; i < 8; i++)
        #pragma unroll
        for (int j = 0; j < 4; j++) acc[i][j] = 0.f;

    for (int kt = 0; kt < Dm; kt += 32) {
        #pragma unroll
        for (int i = 0; i < 16; i++) {           // x tile 128x32
            int idx = i*256 + tid;
            int row = idx >> 5, kc = idx & 31;
            xs[kc*132 + row] = x[(size_t)(m0+row)*Dm + kt + kc];
        }
        #pragma unroll
        for (int i = 0; i < 8; i++) {            // W tile 64x32
            int idx = i*256 + tid;
            int col = idx >> 5, kc = idx & 31;
            ws[kc*68 + col] = W[(size_t)(n0+col)*Dm + kt + kc];
        }
        __syncthreads();
        #pragma unroll 8
        for (int kk = 0; kk < 32; kk++) {        // ascending k, single chain
            float4 a0 = *(const float4*)&xs[kk*132 + ty*8];
            float4 a1 = *(const float4*)&xs[kk*132 + ty*8 + 4];
            float4 b4 = *(const float4*)&ws[kk*68  + tx*4];
            float a[8] = {a0.x,a0.y,a0.z,a0.w,a1.x,a1.y,a1.z,a1.w};
            float b[4] = {b4.x,b4.y,b4.z,b4.w};
            #pragma unroll
            for (int i = 0; i < 8; i++)
                #pragma unroll
                for (int j = 0; j < 4; j++)
                    acc[i][j] = fmaf(a[i], b[j], acc[i][j]);
        }
        __syncthreads();
    }

    #pragma unroll
    for (int i = 0; i < 8; i++) {
        int m  = m0 + ty*8 + i;
        int b_ = m >> 11;          // /2048
        int s_ = m & 2047;
        float* orow = out + ((size_t)(b_*NH + head)*SEQ + s_)*Dh + tx*4;
        #pragma unroll
        for (int j = 0; j < 4; j++)
            orow[j] = acc[i][j] + bias[n0 + tx*4 + j];   // single trailing add
    }
}

// ---------------------------------------------------------------------------
// Fused attention: scores (fp32, canonical in-order FMA chain over d)
// -> running top-10 -> softmax -> dense attn row write -> context.
// Block: 256 threads = 8 warps; 64 query rows (8 per warp); K chunks of 128.
// ---------------------------------------------------------------------------
__global__ __launch_bounds__(256) void attn_kernel(float* __restrict__ out)
{
    extern __shared__ char smraw[];
    float4* Ks4  = (float4*)smraw;                              // [16 jj][129]
    float4* Qs4  = (float4*)(smraw + 16*129*16);                // [64 row][16 jj]
    float*  tval = (float*) (smraw + 16*129*16 + 64*16*16);     // [64][10]
    int*    tidx = (int*)   (tval + 64*TOPK);                   // [64][10]

    const int bh   = blockIdx.x;        // 0..31
    const int q0   = blockIdx.y * 64;   // query tile base
    const int tid  = threadIdx.x;
    const int lane = tid & 31;
    const int w    = tid >> 5;
    const float scale = 0.125f;         // 1/sqrt(64), exact power of 2

    for (int i = tid; i < 64*TOPK; i += 256) { tval[i] = -CUDART_INF_F; tidx[i] = 0; }

    const float4* Qg4 = (const float4*)(g_Q + ((size_t)bh*SEQ + q0)*Dh);
    for (int i = tid; i < 64*16; i += 256) Qs4[i] = Qg4[i];
    __syncthreads();

    #pragma unroll 1
    for (int chunk = 0; chunk < 16; chunk++) {
        const float4* Kg4 = (const float4*)(g_K + ((size_t)bh*SEQ + chunk*128)*Dh);
        for (int i = tid; i < 128*16; i += 256) {
            int key = i >> 4, jj = i & 15;
            Ks4[jj*129 + key] = Kg4[i];
        }
        __syncthreads();

        // score tile: warp w computes rows w*8..w*8+7 vs keys c*32+lane
        // single in-order FMA chain over d = 4*jj + {0,1,2,3}, jj ascending
        float acc[8][4];
        #pragma unroll
        for (int r = 0; r < 8; r++)
            #pragma unroll
            for (int c = 0; c < 4; c++) acc[r][c] = 0.f;

        #pragma unroll 4
        for (int jj = 0; jj < 16; jj++) {
            float4 kv[4];
            kv[0] = Ks4[jj*129 +       lane];
            kv[1] = Ks4[jj*129 + 32  + lane];
            kv[2] = Ks4[jj*129 + 64  + lane];
            kv[3] = Ks4[jj*129 + 96  + lane];
            #pragma unroll
            for (int r = 0; r < 8; r++) {
                float4 q = Qs4[(w*8+r)*16 + jj];
                #pragma unroll
                for (int c = 0; c < 4; c++) {
                    float s = acc[r][c];
                    s = fmaf(q.x, kv[c].x, s);
                    s = fmaf(q.y, kv[c].y, s);
                    s = fmaf(q.z, kv[c].z, s);
                    s = fmaf(q.w, kv[c].w, s);
                    acc[r][c] = s;
                }
            }
        }

        // running top-10 update per row (ballot vs current 10th value);
        // key order ascending -> stable lowest-index tie-breaking like top_k
        for (int r = 0; r < 8; r++) {
            int row = w*8 + r;
            float thr = tval[row*TOPK + 9];
            #pragma unroll
            for (int c = 0; c < 4; c++) {
                float v = acc[r][c] * scale;
                int key = chunk*128 + c*32 + lane;
                unsigned m = __ballot_sync(0xffffffffu, v > thr);
                while (m) {
                    int src = __ffs(m) - 1; m &= m - 1;
                    float vv = __shfl_sync(0xffffffffu, v, src);
                    int   kk = __shfl_sync(0xffffffffu, key, src);
                    if (vv > thr) {
                        if (lane == 0) {
                            int p = 9;
                            while (p > 0 && tval[row*TOPK + p - 1] < vv) {
                                tval[row*TOPK + p] = tval[row*TOPK + p - 1];
                                tidx[row*TOPK + p] = tidx[row*TOPK + p - 1];
                                p--;
                            }
                            tval[row*TOPK + p] = vv;
                            tidx[row*TOPK + p] = kk;
                        }
                        __syncwarp();
                        thr = tval[row*TOPK + 9];
                    }
                }
            }
        }
        __syncthreads();
    }

    // finalize: softmax over top-10, write dense attn row + context
    for (int r = 0; r < 8; r++) {
        int row = w*8 + r;
        int q   = q0 + row;
        float v = (lane < TOPK) ? tval[row*TOPK + lane] : -CUDART_INF_F;
        int  ix = (lane < TOPK) ? tidx[row*TOPK + lane] : 0;
        float mx = tval[row*TOPK + 0];           // sorted desc -> max
        float e = (lane < TOPK) ? expf(v - mx) : 0.f;
        float ssum = e;
        #pragma unroll
        for (int off = 16; off > 0; off >>= 1)
            ssum += __shfl_xor_sync(0xffffffffu, ssum, off);
        float p = e / ssum;

        float pw[TOPK]; int iw[TOPK];
        #pragma unroll
        for (int t = 0; t < TOPK; t++) {
            pw[t] = __shfl_sync(0xffffffffu, p,  t);
            iw[t] = __shfl_sync(0xffffffffu, ix, t);
        }

        // context: dims lane and lane+32, sum of 10 weighted V rows
        float c0 = 0.f, c1 = 0.f;
        #pragma unroll
        for (int t = 0; t < TOPK; t++) {
            const float* vp = g_V + ((size_t)bh*SEQ + iw[t])*Dh;
            c0 = fmaf(pw[t], vp[lane],      c0);
            c1 = fmaf(pw[t], vp[lane + 32], c1);
        }
        int b_ = bh >> 3, h_ = bh & 7;
        size_t co = ((size_t)(b_*SEQ + q))*Dm + h_*Dh;
        out[co + lane]      = c0;
        out[co + lane + 32] = c1;

        // dense attn row: zeros except top-10 (fuses the zero-fill)
        float4* arow4 = (float4*)(out + CTX_ELEMS + ((size_t)bh*SEQ + q)*SEQ);
        #pragma unroll 4
        for (int st = 0; st < 16; st++) {
            bool any = false;
            #pragma unroll
            for (int t = 0; t < TOPK; t++) any |= ((iw[t] >> 7) == st);
            float4 rv = make_float4(0.f, 0.f, 0.f, 0.f);
            if (any) {
                int cbase = st*128 + lane*4;
                #pragma unroll
                for (int t = 0; t < TOPK; t++) {
                    rv.x = (iw[t] == cbase    ) ? pw[t] : rv.x;
                    rv.y = (iw[t] == cbase + 1) ? pw[t] : rv.y;
                    rv.z = (iw[t] == cbase + 2) ? pw[t] : rv.z;
                    rv.w = (iw[t] == cbase + 3) ? pw[t] : rv.w;
                }
            }
            arow4[st*32 + lane] = rv;
        }
    }
}

// ---------------------------------------------------------------------------
extern "C" void kernel_launch(void* const* d_in, const int* in_sizes, int n_in,
                              void* d_out, int out_size)
{
    const float* x  = (const float*)d_in[0];
    const float* Wq = (const float*)d_in[1];
    const float* bq = (const float*)d_in[2];
    const float* Wk = (const float*)d_in[3];
    const float* bk = (const float*)d_in[4];
    const float* Wv = (const float*)d_in[5];
    const float* bv = (const float*)d_in[6];
    float* out = (float*)d_out;

    const int smem_attn = 16*129*16 + 64*16*16 + 64*TOPK*4 + 64*TOPK*4; // 54,528 B
    cudaFuncSetAttribute(attn_kernel, cudaFuncAttributeMaxDynamicSharedMemorySize, smem_attn);

    qkv_gemm<<<dim3(8, 64, 3), 256>>>(x, Wq, bq, Wk, bk, Wv, bv);
    attn_kernel<<<dim3(BH, SEQ/64), 256, smem_attn>>>(out);
}

// round 4
// speedup vs baseline: 1.1994x; 1.1994x over previous
#include <cuda_runtime.h>
#include <math_constants.h>
#include <math.h>

#define Bsz   4
#define SEQ   2048
#define Dm    512
#define NH    8
#define Dh    64
#define TOPK  10
#define BH    (Bsz*NH)                 // 32
#define CTX_ELEMS ((size_t)Bsz*SEQ*Dm) // 4,194,304

typedef unsigned long long ull;

// Scratch for projected Q/K/V in head-major layout [B*H][S][64]
__device__ float g_Q[BH*SEQ*Dh];
__device__ float g_K[BH*SEQ*Dh];
__device__ float g_V[BH*SEQ*Dh];

// ---- packed f32x2 helpers (Blackwell FFMA2 path; each lane = IEEE fp32 fma) ----
__device__ __forceinline__ ull pk2(float lo, float hi) {
    ull r; asm("mov.b64 %0, {%1, %2};" : "=l"(r) : "f"(lo), "f"(hi)); return r;
}
__device__ __forceinline__ ull fma2(ull a, ull b, ull c) {
    ull d; asm("fma.rn.f32x2 %0, %1, %2, %3;" : "=l"(d) : "l"(a), "l"(b), "l"(c)); return d;
}
__device__ __forceinline__ void unpk2(ull v, float& lo, float& hi) {
    asm("mov.b64 {%0, %1}, %2;" : "=f"(lo), "=f"(hi) : "l"(v));
}

// ---------------------------------------------------------------------------
// QKV projection: out[b,h,s,dd] = sum_k x[b,s,k]*W[h*64+dd,k] + bias
// Packed over ROW pairs: each f32x2 lane is the same in-order FMA chain over
// k=0..511 as the scalar version (bit-identical results).
// ---------------------------------------------------------------------------
__global__ __launch_bounds__(256) void qkv_gemm(
    const float* __restrict__ x,
    const float* __restrict__ Wq, const float* __restrict__ bq,
    const float* __restrict__ Wk, const float* __restrict__ bk,
    const float* __restrict__ Wv, const float* __restrict__ bv)
{
    const float* W; const float* bias; float* out;
    if (blockIdx.z == 0)      { W = Wq; bias = bq; out = g_Q; }
    else if (blockIdx.z == 1) { W = Wk; bias = bk; out = g_K; }
    else                      { W = Wv; bias = bv; out = g_V; }

    __shared__ float xs[32*132];  // xs[kc][row], row<128, pad 132
    __shared__ float ws[32*68];   // ws[kc][col], col<64,  pad 68

    int tid = threadIdx.x;
    int tx = tid & 15, ty = tid >> 4;
    int m0 = blockIdx.y * 128;
    int n0 = blockIdx.x * 64;
    int head = blockIdx.x;

    ull acc2[4][4];               // [row-pair][col]
    #pragma unroll
    for (int i = 0; i < 4; i++)
        #pragma unroll
        for (int j = 0; j < 4; j++) acc2[i][j] = 0ull;

    for (int kt = 0; kt < Dm; kt += 32) {
        #pragma unroll
        for (int i = 0; i < 16; i++) {           // x tile 128x32
            int idx = i*256 + tid;
            int row = idx >> 5, kc = idx & 31;
            xs[kc*132 + row] = x[(size_t)(m0+row)*Dm + kt + kc];
        }
        #pragma unroll
        for (int i = 0; i < 8; i++) {            // W tile 64x32
            int idx = i*256 + tid;
            int col = idx >> 5, kc = idx & 31;
            ws[kc*68 + col] = W[(size_t)(n0+col)*Dm + kt + kc];
        }
        __syncthreads();
        #pragma unroll 8
        for (int kk = 0; kk < 32; kk++) {        // ascending k, single chain
            ulonglong2 a01 = *(const ulonglong2*)&xs[kk*132 + ty*8];
            ulonglong2 a23 = *(const ulonglong2*)&xs[kk*132 + ty*8 + 4];
            float4 b4 = *(const float4*)&ws[kk*68 + tx*4];
            ull ap[4] = {a01.x, a01.y, a23.x, a23.y};
            ull bp[4] = {pk2(b4.x,b4.x), pk2(b4.y,b4.y),
                         pk2(b4.z,b4.z), pk2(b4.w,b4.w)};
            #pragma unroll
            for (int i = 0; i < 4; i++)
                #pragma unroll
                for (int j = 0; j < 4; j++)
                    acc2[i][j] = fma2(ap[i], bp[j], acc2[i][j]);
        }
        __syncthreads();
    }

    #pragma unroll
    for (int i = 0; i < 8; i++) {
        int m  = m0 + ty*8 + i;
        int b_ = m >> 11;          // /2048
        int s_ = m & 2047;
        float* orow = out + ((size_t)(b_*NH + head)*SEQ + s_)*Dh + tx*4;
        #pragma unroll
        for (int j = 0; j < 4; j++) {
            float lo, hi; unpk2(acc2[i>>1][j], lo, hi);
            float v = (i & 1) ? hi : lo;
            orow[j] = v + bias[n0 + tx*4 + j];   // single trailing add
        }
    }
}

// ---------------------------------------------------------------------------
// Fused attention: packed-f32x2 scores (each lane = canonical in-order FMA
// chain over d) -> running top-10 -> softmax -> dense attn row -> context.
// Block: 256 threads = 8 warps; 64 query rows (8/warp, packed in row pairs);
// K chunks of 128 keys.
// ---------------------------------------------------------------------------
__global__ __launch_bounds__(256) void attn_kernel(float* __restrict__ out)
{
    extern __shared__ char smraw[];
    float4* Ks4  = (float4*)smraw;                                // [16 jj][129]
    float*  Qt   = (float*) (smraw + 16*129*16);                  // [64 dd][68]
    float*  tval = (float*) (smraw + 16*129*16 + 64*68*4);        // [64][10]
    int*    tidx = (int*)   (tval + 64*TOPK);                     // [64][10]

    const int bh   = blockIdx.x;        // 0..31
    const int q0   = blockIdx.y * 64;   // query tile base
    const int tid  = threadIdx.x;
    const int lane = tid & 31;
    const int w    = tid >> 5;
    const float scale = 0.125f;         // 1/sqrt(64), exact power of 2

    for (int i = tid; i < 64*TOPK; i += 256) { tval[i] = -CUDART_INF_F; tidx[i] = 0; }

    // Q transposed into smem: Qt[dd][row]  (row pairs contiguous)
    {
        const float* Qg = g_Q + ((size_t)bh*SEQ + q0)*Dh;
        for (int i = tid; i < 64*64; i += 256) {
            int row = i >> 6, dd = i & 63;
            Qt[dd*68 + row] = Qg[row*Dh + dd];
        }
    }
    __syncthreads();

    #pragma unroll 1
    for (int chunk = 0; chunk < 16; chunk++) {
        const float4* Kg4 = (const float4*)(g_K + ((size_t)bh*SEQ + chunk*128)*Dh);
        for (int i = tid; i < 128*16; i += 256) {
            int key = i >> 4, jj = i & 15;
            Ks4[jj*129 + key] = Kg4[i];
        }
        __syncthreads();

        // warp w: rows w*8..w*8+7 (4 packed pairs) vs keys c*32+lane (c=0..3)
        // chain over d = 4*jj + dd, jj outer asc, dd inner asc -> global asc
        ull acc2[4][4];                 // [row-pair][c]
        #pragma unroll
        for (int rp = 0; rp < 4; rp++)
            #pragma unroll
            for (int c = 0; c < 4; c++) acc2[rp][c] = 0ull;

        #pragma unroll 2
        for (int jj = 0; jj < 16; jj++) {
            float4 kv[4];
            kv[0] = Ks4[jj*129 +       lane];
            kv[1] = Ks4[jj*129 + 32  + lane];
            kv[2] = Ks4[jj*129 + 64  + lane];
            kv[3] = Ks4[jj*129 + 96  + lane];
            #pragma unroll
            for (int dd = 0; dd < 4; dd++) {
                const float* qrow = &Qt[(4*jj + dd)*68 + w*8];
                ulonglong2 qa = *(const ulonglong2*)qrow;        // rows 0-3
                ulonglong2 qb = *(const ulonglong2*)(qrow + 4);  // rows 4-7
                ull qp[4] = {qa.x, qa.y, qb.x, qb.y};
                float k0 = dd==0?kv[0].x : dd==1?kv[0].y : dd==2?kv[0].z : kv[0].w;
                float k1 = dd==0?kv[1].x : dd==1?kv[1].y : dd==2?kv[1].z : kv[1].w;
                float k2 = dd==0?kv[2].x : dd==1?kv[2].y : dd==2?kv[2].z : kv[2].w;
                float k3 = dd==0?kv[3].x : dd==1?kv[3].y : dd==2?kv[3].z : kv[3].w;
                ull kp[4] = {pk2(k0,k0), pk2(k1,k1), pk2(k2,k2), pk2(k3,k3)};
                #pragma unroll
                for (int rp = 0; rp < 4; rp++)
                    #pragma unroll
                    for (int c = 0; c < 4; c++)
                        acc2[rp][c] = fma2(qp[rp], kp[c], acc2[rp][c]);
            }
        }

        // unpack packed accumulators to per-row scalars
        float sc[8][4];
        #pragma unroll
        for (int rp = 0; rp < 4; rp++)
            #pragma unroll
            for (int c = 0; c < 4; c++)
                unpk2(acc2[rp][c], sc[2*rp][c], sc[2*rp+1][c]);

        // running top-10 update per row (ballot vs current 10th value);
        // ascending key order -> stable lowest-index tie-breaking like top_k
        for (int r = 0; r < 8; r++) {
            int row = w*8 + r;
            float thr = tval[row*TOPK + 9];
            #pragma unroll
            for (int c = 0; c < 4; c++) {
                float v = sc[r][c] * scale;
                int key = chunk*128 + c*32 + lane;
                unsigned m = __ballot_sync(0xffffffffu, v > thr);
                while (m) {
                    int src = __ffs(m) - 1; m &= m - 1;
                    float vv = __shfl_sync(0xffffffffu, v, src);
                    int   kk = __shfl_sync(0xffffffffu, key, src);
                    if (vv > thr) {
                        if (lane == 0) {
                            int p = 9;
                            while (p > 0 && tval[row*TOPK + p - 1] < vv) {
                                tval[row*TOPK + p] = tval[row*TOPK + p - 1];
                                tidx[row*TOPK + p] = tidx[row*TOPK + p - 1];
                                p--;
                            }
                            tval[row*TOPK + p] = vv;
                            tidx[row*TOPK + p] = kk;
                        }
                        __syncwarp();
                        thr = tval[row*TOPK + 9];
                    }
                }
            }
        }
        __syncthreads();
    }

    // finalize: softmax over top-10, write dense attn row + context
    for (int r = 0; r < 8; r++) {
        int row = w*8 + r;
        int q   = q0 + row;
        float v = (lane < TOPK) ? tval[row*TOPK + lane] : -CUDART_INF_F;
        int  ix = (lane < TOPK) ? tidx[row*TOPK + lane] : 0;
        float mx = tval[row*TOPK + 0];           // sorted desc -> max
        float e = (lane < TOPK) ? expf(v - mx) : 0.f;
        float ssum = e;
        #pragma unroll
        for (int off = 16; off > 0; off >>= 1)
            ssum += __shfl_xor_sync(0xffffffffu, ssum, off);
        float p = e / ssum;

        float pw[TOPK]; int iw[TOPK];
        #pragma unroll
        for (int t = 0; t < TOPK; t++) {
            pw[t] = __shfl_sync(0xffffffffu, p,  t);
            iw[t] = __shfl_sync(0xffffffffu, ix, t);
        }

        // context: dims lane and lane+32, sum of 10 weighted V rows
        float c0 = 0.f, c1 = 0.f;
        #pragma unroll
        for (int t = 0; t < TOPK; t++) {
            const float* vp = g_V + ((size_t)bh*SEQ + iw[t])*Dh;
            c0 = fmaf(pw[t], vp[lane],      c0);
            c1 = fmaf(pw[t], vp[lane + 32], c1);
        }
        int b_ = bh >> 3, h_ = bh & 7;
        size_t co = ((size_t)(b_*SEQ + q))*Dm + h_*Dh;
        out[co + lane]      = c0;
        out[co + lane + 32] = c1;

        // dense attn row: zeros except top-10 (fuses the zero-fill)
        float4* arow4 = (float4*)(out + CTX_ELEMS + ((size_t)bh*SEQ + q)*SEQ);
        #pragma unroll 4
        for (int st = 0; st < 16; st++) {
            bool any = false;
            #pragma unroll
            for (int t = 0; t < TOPK; t++) any |= ((iw[t] >> 7) == st);
            float4 rv = make_float4(0.f, 0.f, 0.f, 0.f);
            if (any) {
                int cbase = st*128 + lane*4;
                #pragma unroll
                for (int t = 0; t < TOPK; t++) {
                    rv.x = (iw[t] == cbase    ) ? pw[t] : rv.x;
                    rv.y = (iw[t] == cbase + 1) ? pw[t] : rv.y;
                    rv.z = (iw[t] == cbase + 2) ? pw[t] : rv.z;
                    rv.w = (iw[t] == cbase + 3) ? pw[t] : rv.w;
                }
            }
            arow4[st*32 + lane] = rv;
        }
    }
}

// ---------------------------------------------------------------------------
extern "C" void kernel_launch(void* const* d_in, const int* in_sizes, int n_in,
                              void* d_out, int out_size)
{
    const float* x  = (const float*)d_in[0];
    const float* Wq = (const float*)d_in[1];
    const float* bq = (const float*)d_in[2];
    const float* Wk = (const float*)d_in[3];
    const float* bk = (const float*)d_in[4];
    const float* Wv = (const float*)d_in[5];
    const float* bv = (const float*)d_in[6];
    float* out = (float*)d_out;

    const int smem_attn = 16*129*16 + 64*68*4 + 64*TOPK*4 + 64*TOPK*4; // 55,552 B
    cudaFuncSetAttribute(attn_kernel, cudaFuncAttributeMaxDynamicSharedMemorySize, smem_attn);

    qkv_gemm<<<dim3(8, 64, 3), 256>>>(x, Wq, bq, Wk, bk, Wv, bv);
    attn_kernel<<<dim3(BH, SEQ/64), 256, smem_attn>>>(out);
}